// round 3
// baseline (speedup 1.0000x reference)
#include <cuda_runtime.h>

#define N_NODES 100000
#define N_EDGES 1000000
#define D 64

// Scratch (no allocations allowed): device globals. float4 => 16B alignment
// guaranteed for all wide loads/stores/reductions.
__device__ float4 g_y4[(size_t)N_NODES * (D / 4)];    // message MLP output
__device__ float4 g_agg4[(size_t)N_NODES * (D / 4)];  // scatter-sum accumulator
__device__ int    g_ei_is64;                          // 1 if edge_index is int64

// ---------------------------------------------------------------------------
// K0: zero agg + detect edge_index dtype.
// int64 little-endian with values < 2^31 => every odd 32-bit word is 0.
// For a genuine int32 index array, 64 consecutive random indices all being
// zero is impossible in practice.
// ---------------------------------------------------------------------------
__global__ void k_zero_agg(const int* __restrict__ ei32) {
    int idx = blockIdx.x * blockDim.x + threadIdx.x;
    const int n4 = N_NODES * (D / 4);
    if (idx < n4) {
        g_agg4[idx] = make_float4(0.f, 0.f, 0.f, 0.f);
    }
    if (blockIdx.x == 0 && threadIdx.x == 0) {
        int is64 = 1;
        for (int i = 0; i < 64; i++) {
            if (ei32[2 * i + 1] != 0) { is64 = 0; break; }
        }
        g_ei_is64 = is64;
    }
}

// ---------------------------------------------------------------------------
// K1: node message MLP  y = relu(x @ W1 + b1) @ W2 + b2      [N,64]
// One node per thread; 256 nodes per block. x tile staged in shared with
// odd-stride padding (65) -> conflict-free per-lane reads. Weights broadcast
// from shared (uniform address across warp -> multicast).
// ---------------------------------------------------------------------------
#define K1_SMEM_FLOATS (256 * 65 + 4096 + 4096 + 64 + 64)

__global__ __launch_bounds__(256) void k_msg_mlp(
    const float* __restrict__ x,
    const float* __restrict__ w1, const float* __restrict__ b1,
    const float* __restrict__ w2, const float* __restrict__ b2)
{
    extern __shared__ float sm[];
    float* xs  = sm;               // 256 * 65
    float* w1s = xs + 256 * 65;    // 64*64
    float* w2s = w1s + 4096;       // 64*64
    float* b1s = w2s + 4096;       // 64
    float* b2s = b1s + 64;         // 64

    const int tid = threadIdx.x;
    const int n0  = blockIdx.x * 256;

    for (int i = tid; i < 4096 / 4; i += 256) {
        ((float4*)w1s)[i] = ((const float4*)w1)[i];
        ((float4*)w2s)[i] = ((const float4*)w2)[i];
    }
    if (tid < 64) { b1s[tid] = b1[tid]; b2s[tid] = b2[tid]; }

    const float4* x4 = (const float4*)(x + (size_t)n0 * D);
    for (int i = tid; i < (256 * D) / 4; i += 256) {
        int elem = i * 4;
        int l = elem >> 6, k = elem & 63;
        float4 v = make_float4(0.f, 0.f, 0.f, 0.f);
        if (n0 + l < N_NODES) v = x4[i];
        float* p = xs + l * 65 + k;
        p[0] = v.x; p[1] = v.y; p[2] = v.z; p[3] = v.w;
    }
    __syncthreads();

    const int n = n0 + tid;

    float h[D];
#pragma unroll
    for (int j = 0; j < D; j++) h[j] = b1s[j];

    const float* xr = xs + tid * 65;
#pragma unroll 2
    for (int k = 0; k < D; k++) {
        float v = xr[k];
        const float4* wr = (const float4*)(w1s + k * D);
#pragma unroll
        for (int j = 0; j < D / 4; j++) {
            float4 w = wr[j];
            h[4 * j + 0] += v * w.x;
            h[4 * j + 1] += v * w.y;
            h[4 * j + 2] += v * w.z;
            h[4 * j + 3] += v * w.w;
        }
    }
#pragma unroll
    for (int j = 0; j < D; j++) h[j] = fmaxf(h[j], 0.f);

    if (n < N_NODES) {
        float4* yrow = g_y4 + (size_t)n * (D / 4);
        for (int jc = 0; jc < D; jc += 16) {
            float acc[16];
#pragma unroll
            for (int t = 0; t < 16; t++) acc[t] = b2s[jc + t];
#pragma unroll
            for (int k = 0; k < D; k++) {
                float v = h[k];
                const float4* wr = (const float4*)(w2s + k * D + jc);
#pragma unroll
                for (int t = 0; t < 4; t++) {
                    float4 w = wr[t];
                    acc[4 * t + 0] += v * w.x;
                    acc[4 * t + 1] += v * w.y;
                    acc[4 * t + 2] += v * w.z;
                    acc[4 * t + 3] += v * w.w;
                }
            }
#pragma unroll
            for (int t = 0; t < 4; t++) {
                yrow[jc / 4 + t] =
                    make_float4(acc[4 * t], acc[4 * t + 1], acc[4 * t + 2], acc[4 * t + 3]);
            }
        }
    }
}

// ---------------------------------------------------------------------------
// K2: scatter  agg[col] += y[row]  via red.global.add.v4.f32
// 16 threads per edge, one float4 reduction each. Handles int64 or int32
// edge_index via runtime flag; OOB indices skipped (never crash).
// ---------------------------------------------------------------------------
__global__ __launch_bounds__(256) void k_scatter(const void* __restrict__ ei_raw)
{
    long long tid = (long long)blockIdx.x * blockDim.x + threadIdx.x;
    if (tid >= (long long)N_EDGES * 16) return;
    int e = (int)(tid >> 4);
    int c = (int)(tid & 15);

    int row, col;
    if (g_ei_is64) {
        const long long* ei = (const long long*)ei_raw;
        row = (int)ei[e];
        col = (int)ei[N_EDGES + e];
    } else {
        const int* ei = (const int*)ei_raw;
        row = ei[e];
        col = ei[N_EDGES + e];
    }
    if ((unsigned)row >= N_NODES || (unsigned)col >= N_NODES) return;

    const float4 v = g_y4[(size_t)row * (D / 4) + c];
    float4* p = g_agg4 + (size_t)col * (D / 4) + c;
    asm volatile("red.global.add.v4.f32 [%0], {%1,%2,%3,%4};"
                 :: "l"(p), "f"(v.x), "f"(v.y), "f"(v.z), "f"(v.w)
                 : "memory");
}

// ---------------------------------------------------------------------------
// K3: output MLP  out = relu([x,agg] @ W1 + b1) @ W2 + b2     [N,64]
// ---------------------------------------------------------------------------
#define K3_SMEM_FLOATS (256 * 129 + 8192 + 4096 + 64 + 64)

__global__ __launch_bounds__(256) void k_out_mlp(
    const float* __restrict__ x,
    const float* __restrict__ w1, const float* __restrict__ b1,
    const float* __restrict__ w2, const float* __restrict__ b2,
    float* __restrict__ out)
{
    extern __shared__ float sm[];
    float* cs  = sm;               // 256 * 129 (concat rows)
    float* w1s = cs + 256 * 129;   // 128*64
    float* w2s = w1s + 8192;       // 64*64
    float* b1s = w2s + 4096;       // 64
    float* b2s = b1s + 64;         // 64

    const int tid = threadIdx.x;
    const int n0  = blockIdx.x * 256;

    for (int i = tid; i < 8192 / 4; i += 256)
        ((float4*)w1s)[i] = ((const float4*)w1)[i];
    for (int i = tid; i < 4096 / 4; i += 256)
        ((float4*)w2s)[i] = ((const float4*)w2)[i];
    if (tid < 64) { b1s[tid] = b1[tid]; b2s[tid] = b2[tid]; }

    const float4* x4 = (const float4*)(x + (size_t)n0 * D);
    const float4* a4 = g_agg4 + (size_t)n0 * (D / 4);
    for (int i = tid; i < (256 * D) / 4; i += 256) {
        int elem = i * 4;
        int l = elem >> 6, k = elem & 63;
        float4 v = make_float4(0.f, 0.f, 0.f, 0.f);
        float4 a = make_float4(0.f, 0.f, 0.f, 0.f);
        if (n0 + l < N_NODES) { v = x4[i]; a = a4[i]; }
        float* p = cs + l * 129 + k;
        p[0] = v.x; p[1] = v.y; p[2] = v.z; p[3] = v.w;
        float* q = p + 64;
        q[0] = a.x; q[1] = a.y; q[2] = a.z; q[3] = a.w;
    }
    __syncthreads();

    const int n = n0 + tid;

    float t[D];
#pragma unroll
    for (int j = 0; j < D; j++) t[j] = b1s[j];

    const float* cr = cs + tid * 129;
#pragma unroll 2
    for (int k = 0; k < 2 * D; k++) {
        float v = cr[k];
        const float4* wr = (const float4*)(w1s + k * D);
#pragma unroll
        for (int j = 0; j < D / 4; j++) {
            float4 w = wr[j];
            t[4 * j + 0] += v * w.x;
            t[4 * j + 1] += v * w.y;
            t[4 * j + 2] += v * w.z;
            t[4 * j + 3] += v * w.w;
        }
    }
#pragma unroll
    for (int j = 0; j < D; j++) t[j] = fmaxf(t[j], 0.f);

    if (n < N_NODES) {
        float* orow = out + (size_t)n * D;
        for (int jc = 0; jc < D; jc += 16) {
            float acc[16];
#pragma unroll
            for (int tt = 0; tt < 16; tt++) acc[tt] = b2s[jc + tt];
#pragma unroll
            for (int k = 0; k < D; k++) {
                float v = t[k];
                const float4* wr = (const float4*)(w2s + k * D + jc);
#pragma unroll
                for (int tt = 0; tt < 4; tt++) {
                    float4 w = wr[tt];
                    acc[4 * tt + 0] += v * w.x;
                    acc[4 * tt + 1] += v * w.y;
                    acc[4 * tt + 2] += v * w.z;
                    acc[4 * tt + 3] += v * w.w;
                }
            }
#pragma unroll
            for (int tt = 0; tt < 16; tt += 4) {
                orow[jc + tt + 0] = acc[tt + 0];
                orow[jc + tt + 1] = acc[tt + 1];
                orow[jc + tt + 2] = acc[tt + 2];
                orow[jc + tt + 3] = acc[tt + 3];
            }
        }
    }
}

// ---------------------------------------------------------------------------
// Launch. Inputs (metadata order): 0 x, 1 edge_index, 2 batch,
// 3 msg_w1, 4 msg_b1, 5 msg_w2, 6 msg_b2, 7 out_w1, 8 out_b1, 9 out_w2, 10 out_b2
// ---------------------------------------------------------------------------
extern "C" void kernel_launch(void* const* d_in, const int* in_sizes, int n_in,
                              void* d_out, int out_size)
{
    const float* x      = (const float*)d_in[0];
    const void*  ei     = d_in[1];
    const float* msg_w1 = (const float*)d_in[3];
    const float* msg_b1 = (const float*)d_in[4];
    const float* msg_w2 = (const float*)d_in[5];
    const float* msg_b2 = (const float*)d_in[6];
    const float* out_w1 = (const float*)d_in[7];
    const float* out_b1 = (const float*)d_in[8];
    const float* out_w2 = (const float*)d_in[9];
    const float* out_b2 = (const float*)d_in[10];
    float*       out    = (float*)d_out;

    const int smem1 = K1_SMEM_FLOATS * sizeof(float);   // ~99.8 KB
    const int smem3 = K3_SMEM_FLOATS * sizeof(float);   // ~181.8 KB
    cudaFuncSetAttribute(k_msg_mlp, cudaFuncAttributeMaxDynamicSharedMemorySize, smem1);
    cudaFuncSetAttribute(k_out_mlp, cudaFuncAttributeMaxDynamicSharedMemorySize, smem3);

    const int nodeBlocks = (N_NODES + 255) / 256;

    k_zero_agg<<<(N_NODES * D / 4 + 255) / 256, 256>>>((const int*)ei);
    k_msg_mlp<<<nodeBlocks, 256, smem1>>>(x, msg_w1, msg_b1, msg_w2, msg_b2);
    {
        long long work = (long long)N_EDGES * 16;
        int blocks = (int)((work + 255) / 256);
        k_scatter<<<blocks, 256>>>(ei);
    }
    k_out_mlp<<<nodeBlocks, 256, smem3>>>(x, out_w1, out_b1, out_w2, out_b2, out);
}

// round 4
// speedup vs baseline: 1.0288x; 1.0288x over previous
#include <cuda_runtime.h>

#define N_NODES 100000
#define N_EDGES 1000000
#define D 64

// Scratch: device globals (no allocs allowed). float4 => 16B aligned.
__device__ float4 g_y4[(size_t)N_NODES * (D / 4)];    // message MLP output
__device__ float4 g_agg4[(size_t)N_NODES * (D / 4)];  // scatter-sum accumulator
__device__ int    g_ei_is64;                          // 1 if edge_index is int64

// Rotation swizzle: row l, col k stored at (l<<6) | ((k+l)&63).
// Lane read (same k, lanes = consecutive l) -> bank (k+l)%64 %32 distinct
// within each 32-lane group -> conflict-free at stride 64 (no padding).
__device__ __forceinline__ int swz(int l, int k) { return (l << 6) | ((k + l) & 63); }

// ---------------------------------------------------------------------------
// K0: zero agg + detect edge_index dtype (int64 LE => odd 32-bit words == 0)
// ---------------------------------------------------------------------------
__global__ void k_zero_agg(const int* __restrict__ ei32) {
    int idx = blockIdx.x * blockDim.x + threadIdx.x;
    const int n4 = N_NODES * (D / 4);
    if (idx < n4) g_agg4[idx] = make_float4(0.f, 0.f, 0.f, 0.f);
    if (blockIdx.x == 0 && threadIdx.x == 0) {
        int is64 = 1;
        for (int i = 0; i < 64; i++)
            if (ei32[2 * i + 1] != 0) { is64 = 0; break; }
        g_ei_is64 = is64;
    }
}

// ---------------------------------------------------------------------------
// K1: node message MLP  y = relu(x @ W1 + b1) @ W2 + b2      [N,64]
// 1 node/thread, 256 thr/block, 2 CTAs/SM (<=128 regs, 96.5KB smem).
// ---------------------------------------------------------------------------
#define K1_SMEM_FLOATS (256 * 64 + 4096 + 4096 + 64 + 64)

__global__ __launch_bounds__(256, 2) void k_msg_mlp(
    const float* __restrict__ x,
    const float* __restrict__ w1, const float* __restrict__ b1,
    const float* __restrict__ w2, const float* __restrict__ b2)
{
    extern __shared__ float sm[];
    float* xs  = sm;               // 256*64 swizzled tile
    float* w1s = xs + 256 * 64;    // 64*64
    float* w2s = w1s + 4096;       // 64*64
    float* b1s = w2s + 4096;       // 64
    float* b2s = b1s + 64;         // 64

    const int tid = threadIdx.x;
    const int n0  = blockIdx.x * 256;

    for (int i = tid; i < 4096 / 4; i += 256) {
        ((float4*)w1s)[i] = ((const float4*)w1)[i];
        ((float4*)w2s)[i] = ((const float4*)w2)[i];
    }
    if (tid < 64) { b1s[tid] = b1[tid]; b2s[tid] = b2[tid]; }

    // Stage x tile (coalesced gmem float4 -> swizzled scalar smem stores)
    const float4* x4 = (const float4*)(x + (size_t)n0 * D);
    for (int i = tid; i < (256 * D) / 4; i += 256) {
        int elem = i * 4;
        int l = elem >> 6, k = elem & 63;
        float4 v = make_float4(0.f, 0.f, 0.f, 0.f);
        if (n0 + l < N_NODES) v = x4[i];
        xs[swz(l, k + 0)] = v.x;
        xs[swz(l, k + 1)] = v.y;
        xs[swz(l, k + 2)] = v.z;
        xs[swz(l, k + 3)] = v.w;
    }
    __syncthreads();

    const int n = n0 + tid;

    float h[D];
#pragma unroll
    for (int j = 0; j < D; j++) h[j] = b1s[j];

#pragma unroll 2
    for (int k = 0; k < D; k++) {
        float v = xs[swz(tid, k)];
        const float4* wr = (const float4*)(w1s + k * D);
#pragma unroll
        for (int j = 0; j < D / 4; j++) {
            float4 w = wr[j];
            h[4 * j + 0] += v * w.x;
            h[4 * j + 1] += v * w.y;
            h[4 * j + 2] += v * w.z;
            h[4 * j + 3] += v * w.w;
        }
    }
#pragma unroll
    for (int j = 0; j < D; j++) h[j] = fmaxf(h[j], 0.f);

    if (n < N_NODES) {
        float4* yrow = g_y4 + (size_t)n * (D / 4);
        for (int jc = 0; jc < D; jc += 16) {
            float acc[16];
#pragma unroll
            for (int t = 0; t < 16; t++) acc[t] = b2s[jc + t];
#pragma unroll
            for (int k = 0; k < D; k++) {
                float v = h[k];
                const float4* wr = (const float4*)(w2s + k * D + jc);
#pragma unroll
                for (int t = 0; t < 4; t++) {
                    float4 w = wr[t];
                    acc[4 * t + 0] += v * w.x;
                    acc[4 * t + 1] += v * w.y;
                    acc[4 * t + 2] += v * w.z;
                    acc[4 * t + 3] += v * w.w;
                }
            }
#pragma unroll
            for (int t = 0; t < 4; t++)
                yrow[jc / 4 + t] =
                    make_float4(acc[4 * t], acc[4 * t + 1], acc[4 * t + 2], acc[4 * t + 3]);
        }
    }
}

// ---------------------------------------------------------------------------
// K2: scatter  agg[col] += y[row]  via red.global.add.v4.f32
// 16 threads/edge; int64 or int32 indices; OOB guarded.
// ---------------------------------------------------------------------------
__global__ __launch_bounds__(256) void k_scatter(const void* __restrict__ ei_raw)
{
    long long tid = (long long)blockIdx.x * blockDim.x + threadIdx.x;
    if (tid >= (long long)N_EDGES * 16) return;
    int e = (int)(tid >> 4);
    int c = (int)(tid & 15);

    int row, col;
    if (g_ei_is64) {
        const long long* ei = (const long long*)ei_raw;
        row = (int)ei[e];
        col = (int)ei[N_EDGES + e];
    } else {
        const int* ei = (const int*)ei_raw;
        row = ei[e];
        col = ei[N_EDGES + e];
    }
    if ((unsigned)row >= N_NODES || (unsigned)col >= N_NODES) return;

    const float4 v = g_y4[(size_t)row * (D / 4) + c];
    float4* p = g_agg4 + (size_t)col * (D / 4) + c;
    asm volatile("red.global.add.v4.f32 [%0], {%1,%2,%3,%4};"
                 :: "l"(p), "f"(v.x), "f"(v.y), "f"(v.z), "f"(v.w)
                 : "memory");
}

// ---------------------------------------------------------------------------
// K3: output MLP  out = relu([x,agg] @ W1 + b1) @ W2 + b2     [N,64]
// Two-pass layer 1: stage x tile -> accumulate k=0..63, re-stage with agg ->
// accumulate k=64..127. Smem 112.5KB, <=128 regs -> 2 CTAs/SM.
// ---------------------------------------------------------------------------
#define K3_SMEM_FLOATS (256 * 64 + 8192 + 4096 + 64 + 64)

__global__ __launch_bounds__(256, 2) void k_out_mlp(
    const float* __restrict__ x,
    const float* __restrict__ w1, const float* __restrict__ b1,
    const float* __restrict__ w2, const float* __restrict__ b2,
    float* __restrict__ out)
{
    extern __shared__ float sm[];
    float* xs  = sm;               // 256*64 swizzled tile (reused x then agg)
    float* w1s = xs + 256 * 64;    // 128*64
    float* w2s = w1s + 8192;       // 64*64
    float* b1s = w2s + 4096;       // 64
    float* b2s = b1s + 64;         // 64

    const int tid = threadIdx.x;
    const int n0  = blockIdx.x * 256;

    for (int i = tid; i < 8192 / 4; i += 256)
        ((float4*)w1s)[i] = ((const float4*)w1)[i];
    for (int i = tid; i < 4096 / 4; i += 256)
        ((float4*)w2s)[i] = ((const float4*)w2)[i];
    if (tid < 64) { b1s[tid] = b1[tid]; b2s[tid] = b2[tid]; }

    // ---- pass A: x tile ----
    const float4* x4 = (const float4*)(x + (size_t)n0 * D);
    for (int i = tid; i < (256 * D) / 4; i += 256) {
        int elem = i * 4;
        int l = elem >> 6, k = elem & 63;
        float4 v = make_float4(0.f, 0.f, 0.f, 0.f);
        if (n0 + l < N_NODES) v = x4[i];
        xs[swz(l, k + 0)] = v.x;
        xs[swz(l, k + 1)] = v.y;
        xs[swz(l, k + 2)] = v.z;
        xs[swz(l, k + 3)] = v.w;
    }
    __syncthreads();

    float h[D];
#pragma unroll
    for (int j = 0; j < D; j++) h[j] = b1s[j];

#pragma unroll 2
    for (int k = 0; k < D; k++) {
        float v = xs[swz(tid, k)];
        const float4* wr = (const float4*)(w1s + k * D);
#pragma unroll
        for (int j = 0; j < D / 4; j++) {
            float4 w = wr[j];
            h[4 * j + 0] += v * w.x;
            h[4 * j + 1] += v * w.y;
            h[4 * j + 2] += v * w.z;
            h[4 * j + 3] += v * w.w;
        }
    }
    __syncthreads();   // everyone done reading x tile

    // ---- pass B: agg tile (reuse buffer) ----
    const float4* a4 = g_agg4 + (size_t)n0 * (D / 4);
    for (int i = tid; i < (256 * D) / 4; i += 256) {
        int elem = i * 4;
        int l = elem >> 6, k = elem & 63;
        float4 a = make_float4(0.f, 0.f, 0.f, 0.f);
        if (n0 + l < N_NODES) a = a4[i];
        xs[swz(l, k + 0)] = a.x;
        xs[swz(l, k + 1)] = a.y;
        xs[swz(l, k + 2)] = a.z;
        xs[swz(l, k + 3)] = a.w;
    }
    __syncthreads();

#pragma unroll 2
    for (int k = 0; k < D; k++) {
        float v = xs[swz(tid, k)];
        const float4* wr = (const float4*)(w1s + (D + k) * D);
#pragma unroll
        for (int j = 0; j < D / 4; j++) {
            float4 w = wr[j];
            h[4 * j + 0] += v * w.x;
            h[4 * j + 1] += v * w.y;
            h[4 * j + 2] += v * w.z;
            h[4 * j + 3] += v * w.w;
        }
    }
#pragma unroll
    for (int j = 0; j < D; j++) h[j] = fmaxf(h[j], 0.f);

    const int n = n0 + tid;
    if (n < N_NODES) {
        float* orow = out + (size_t)n * D;
        for (int jc = 0; jc < D; jc += 16) {
            float acc[16];
#pragma unroll
            for (int tt = 0; tt < 16; tt++) acc[tt] = b2s[jc + tt];
#pragma unroll
            for (int k = 0; k < D; k++) {
                float v = h[k];
                const float4* wr = (const float4*)(w2s + k * D + jc);
#pragma unroll
                for (int tt = 0; tt < 4; tt++) {
                    float4 w = wr[tt];
                    acc[4 * tt + 0] += v * w.x;
                    acc[4 * tt + 1] += v * w.y;
                    acc[4 * tt + 2] += v * w.z;
                    acc[4 * tt + 3] += v * w.w;
                }
            }
#pragma unroll
            for (int tt = 0; tt < 16; tt++) orow[jc + tt] = acc[tt];
        }
    }
}

// ---------------------------------------------------------------------------
// Launch. Inputs: 0 x, 1 edge_index, 2 batch, 3..6 msg mlp, 7..10 out mlp
// ---------------------------------------------------------------------------
extern "C" void kernel_launch(void* const* d_in, const int* in_sizes, int n_in,
                              void* d_out, int out_size)
{
    const float* x      = (const float*)d_in[0];
    const void*  ei     = d_in[1];
    const float* msg_w1 = (const float*)d_in[3];
    const float* msg_b1 = (const float*)d_in[4];
    const float* msg_w2 = (const float*)d_in[5];
    const float* msg_b2 = (const float*)d_in[6];
    const float* out_w1 = (const float*)d_in[7];
    const float* out_b1 = (const float*)d_in[8];
    const float* out_w2 = (const float*)d_in[9];
    const float* out_b2 = (const float*)d_in[10];
    float*       out    = (float*)d_out;

    const int smem1 = K1_SMEM_FLOATS * sizeof(float);   // 96.5 KB
    const int smem3 = K3_SMEM_FLOATS * sizeof(float);   // 112.5 KB
    cudaFuncSetAttribute(k_msg_mlp, cudaFuncAttributeMaxDynamicSharedMemorySize, smem1);
    cudaFuncSetAttribute(k_out_mlp, cudaFuncAttributeMaxDynamicSharedMemorySize, smem3);

    const int nodeBlocks = (N_NODES + 255) / 256;

    k_zero_agg<<<(N_NODES * D / 4 + 255) / 256, 256>>>((const int*)ei);
    k_msg_mlp<<<nodeBlocks, 256, smem1>>>(x, msg_w1, msg_b1, msg_w2, msg_b2);
    {
        long long work = (long long)N_EDGES * 16;
        int blocks = (int)((work + 255) / 256);
        k_scatter<<<blocks, 256>>>(ei);
    }
    k_out_mlp<<<nodeBlocks, 256, smem3>>>(x, out_w1, out_b1, out_w2, out_b2, out);
}

// round 5
// speedup vs baseline: 1.1172x; 1.0859x over previous
#include <cuda_runtime.h>

#define N_NODES 100000
#define N_EDGES 1000000
#define D 64

// Scratch: device globals (no allocs allowed). float4 => 16B aligned.
__device__ float4 g_y4[(size_t)N_NODES * (D / 4)];    // message MLP output
__device__ float4 g_agg4[(size_t)N_NODES * (D / 4)];  // scatter-sum accumulator
__device__ int    g_ei_is64;                          // 1 if edge_index is int64

// Rotation swizzle: row l, col k stored at (l<<6) | ((k+l)&63) -> conflict-free.
__device__ __forceinline__ int swz(int l, int k) { return (l << 6) | ((k + l) & 63); }

// ---- packed f32x2 helpers (Blackwell dual-FP32 pipe) ----
typedef unsigned long long u64t;

__device__ __forceinline__ u64t pk2(float a, float b) {
    u64t r; asm("mov.b64 %0, {%1, %2};" : "=l"(r) : "f"(a), "f"(b)); return r;
}
__device__ __forceinline__ void upk2(u64t p, float& a, float& b) {
    asm("mov.b64 {%0, %1}, %2;" : "=f"(a), "=f"(b) : "l"(p));
}
__device__ __forceinline__ void fma2(u64t& d, u64t a, u64t b) {
    asm("fma.rn.f32x2 %0, %1, %2, %0;" : "+l"(d) : "l"(a), "l"(b));
}

// ---------------------------------------------------------------------------
// K0: zero agg + detect edge_index dtype (int64 LE => odd 32-bit words == 0)
// ---------------------------------------------------------------------------
__global__ void k_zero_agg(const int* __restrict__ ei32) {
    int idx = blockIdx.x * blockDim.x + threadIdx.x;
    const int n4 = N_NODES * (D / 4);
    if (idx < n4) g_agg4[idx] = make_float4(0.f, 0.f, 0.f, 0.f);
    if (blockIdx.x == 0 && threadIdx.x == 0) {
        int is64 = 1;
        for (int i = 0; i < 64; i++)
            if (ei32[2 * i + 1] != 0) { is64 = 0; break; }
        g_ei_is64 = is64;
    }
}

// ---------------------------------------------------------------------------
// K1: node message MLP  y = relu(x @ W1 + b1) @ W2 + b2      [N,64]
// 1 node/thread, 256 thr/block, f32x2 packed math throughout.
// ---------------------------------------------------------------------------
#define K1_SMEM_FLOATS (256 * 64 + 4096 + 4096 + 64 + 64)

__global__ __launch_bounds__(256, 2) void k_msg_mlp(
    const float* __restrict__ x,
    const float* __restrict__ w1, const float* __restrict__ b1,
    const float* __restrict__ w2, const float* __restrict__ b2)
{
    extern __shared__ float sm[];
    float* xs  = sm;               // 256*64 swizzled tile
    float* w1s = xs + 256 * 64;    // 64*64
    float* w2s = w1s + 4096;       // 64*64
    float* b1s = w2s + 4096;       // 64
    float* b2s = b1s + 64;         // 64

    const int tid = threadIdx.x;
    const int n0  = blockIdx.x * 256;

    for (int i = tid; i < 4096 / 4; i += 256) {
        ((float4*)w1s)[i] = ((const float4*)w1)[i];
        ((float4*)w2s)[i] = ((const float4*)w2)[i];
    }
    if (tid < 64) { b1s[tid] = b1[tid]; b2s[tid] = b2[tid]; }

    const float4* x4 = (const float4*)(x + (size_t)n0 * D);
    for (int i = tid; i < (256 * D) / 4; i += 256) {
        int elem = i * 4;
        int l = elem >> 6, k = elem & 63;
        float4 v = make_float4(0.f, 0.f, 0.f, 0.f);
        if (n0 + l < N_NODES) v = x4[i];
        xs[swz(l, k + 0)] = v.x;
        xs[swz(l, k + 1)] = v.y;
        xs[swz(l, k + 2)] = v.z;
        xs[swz(l, k + 3)] = v.w;
    }
    __syncthreads();

    // ---- layer 1 (packed accumulators: hp[j] = outputs 2j, 2j+1) ----
    u64t hp[32];
    {
        const u64t* b1p = (const u64t*)b1s;
#pragma unroll
        for (int j = 0; j < 32; j++) hp[j] = b1p[j];
    }
#pragma unroll 2
    for (int k = 0; k < D; k++) {
        float v = xs[swz(tid, k)];
        u64t v2 = pk2(v, v);
        const ulonglong2* wr = (const ulonglong2*)(w1s + k * D);
#pragma unroll
        for (int j = 0; j < 16; j++) {
            ulonglong2 w = wr[j];
            fma2(hp[2 * j + 0], v2, w.x);
            fma2(hp[2 * j + 1], v2, w.y);
        }
    }
    float h[D];
#pragma unroll
    for (int j = 0; j < 32; j++) {
        float a, b; upk2(hp[j], a, b);
        h[2 * j + 0] = fmaxf(a, 0.f);
        h[2 * j + 1] = fmaxf(b, 0.f);
    }

    // ---- layer 2 (two chunks of 32 outputs, packed) ----
    const int n = n0 + tid;
    if (n < N_NODES) {
        ulonglong2* yrow = (ulonglong2*)(g_y4 + (size_t)n * (D / 4));
#pragma unroll
        for (int jc = 0; jc < D; jc += 32) {
            u64t acc[16];
            const u64t* b2p = (const u64t*)(b2s + jc);
#pragma unroll
            for (int t = 0; t < 16; t++) acc[t] = b2p[t];
#pragma unroll
            for (int k = 0; k < D; k++) {
                u64t v2 = pk2(h[k], h[k]);
                const ulonglong2* wr = (const ulonglong2*)(w2s + k * D + jc);
#pragma unroll
                for (int t = 0; t < 8; t++) {
                    ulonglong2 w = wr[t];
                    fma2(acc[2 * t + 0], v2, w.x);
                    fma2(acc[2 * t + 1], v2, w.y);
                }
            }
#pragma unroll
            for (int t = 0; t < 8; t++) {
                ulonglong2 st; st.x = acc[2 * t]; st.y = acc[2 * t + 1];
                yrow[jc / 4 + t] = st;
            }
        }
    }
}

// ---------------------------------------------------------------------------
// K2: scatter  agg[col] += y[row]  via red.global.add.v4.f32
// 16 threads/edge; int64 or int32 indices; OOB guarded.
// ---------------------------------------------------------------------------
__global__ __launch_bounds__(256) void k_scatter(const void* __restrict__ ei_raw)
{
    long long tid = (long long)blockIdx.x * blockDim.x + threadIdx.x;
    if (tid >= (long long)N_EDGES * 16) return;
    int e = (int)(tid >> 4);
    int c = (int)(tid & 15);

    int row, col;
    if (g_ei_is64) {
        const long long* ei = (const long long*)ei_raw;
        row = (int)ei[e];
        col = (int)ei[N_EDGES + e];
    } else {
        const int* ei = (const int*)ei_raw;
        row = ei[e];
        col = ei[N_EDGES + e];
    }
    if ((unsigned)row >= N_NODES || (unsigned)col >= N_NODES) return;

    const float4 v = g_y4[(size_t)row * (D / 4) + c];
    float4* p = g_agg4 + (size_t)col * (D / 4) + c;
    asm volatile("red.global.add.v4.f32 [%0], {%1,%2,%3,%4};"
                 :: "l"(p), "f"(v.x), "f"(v.y), "f"(v.z), "f"(v.w)
                 : "memory");
}

// ---------------------------------------------------------------------------
// K3: output MLP  out = relu([x,agg] @ W1 + b1) @ W2 + b2     [N,64]
// Two-pass layer 1 over the shared 256x64 tile (x then agg), f32x2 packed.
// ---------------------------------------------------------------------------
#define K3_SMEM_FLOATS (256 * 64 + 8192 + 4096 + 64 + 64)

__global__ __launch_bounds__(256, 2) void k_out_mlp(
    const float* __restrict__ x,
    const float* __restrict__ w1, const float* __restrict__ b1,
    const float* __restrict__ w2, const float* __restrict__ b2,
    float* __restrict__ out)
{
    extern __shared__ float sm[];
    float* xs  = sm;               // 256*64 swizzled tile (x, then agg)
    float* w1s = xs + 256 * 64;    // 128*64
    float* w2s = w1s + 8192;       // 64*64
    float* b1s = w2s + 4096;       // 64
    float* b2s = b1s + 64;         // 64

    const int tid = threadIdx.x;
    const int n0  = blockIdx.x * 256;

    for (int i = tid; i < 8192 / 4; i += 256)
        ((float4*)w1s)[i] = ((const float4*)w1)[i];
    for (int i = tid; i < 4096 / 4; i += 256)
        ((float4*)w2s)[i] = ((const float4*)w2)[i];
    if (tid < 64) { b1s[tid] = b1[tid]; b2s[tid] = b2[tid]; }

    // ---- pass A: x tile ----
    const float4* x4 = (const float4*)(x + (size_t)n0 * D);
    for (int i = tid; i < (256 * D) / 4; i += 256) {
        int elem = i * 4;
        int l = elem >> 6, k = elem & 63;
        float4 v = make_float4(0.f, 0.f, 0.f, 0.f);
        if (n0 + l < N_NODES) v = x4[i];
        xs[swz(l, k + 0)] = v.x;
        xs[swz(l, k + 1)] = v.y;
        xs[swz(l, k + 2)] = v.z;
        xs[swz(l, k + 3)] = v.w;
    }
    __syncthreads();

    u64t hp[32];
    {
        const u64t* b1p = (const u64t*)b1s;
#pragma unroll
        for (int j = 0; j < 32; j++) hp[j] = b1p[j];
    }
#pragma unroll 2
    for (int k = 0; k < D; k++) {
        float v = xs[swz(tid, k)];
        u64t v2 = pk2(v, v);
        const ulonglong2* wr = (const ulonglong2*)(w1s + k * D);
#pragma unroll
        for (int j = 0; j < 16; j++) {
            ulonglong2 w = wr[j];
            fma2(hp[2 * j + 0], v2, w.x);
            fma2(hp[2 * j + 1], v2, w.y);
        }
    }
    __syncthreads();   // all reads of x tile done

    // ---- pass B: agg tile (reuse buffer) ----
    const float4* a4 = g_agg4 + (size_t)n0 * (D / 4);
    for (int i = tid; i < (256 * D) / 4; i += 256) {
        int elem = i * 4;
        int l = elem >> 6, k = elem & 63;
        float4 a = make_float4(0.f, 0.f, 0.f, 0.f);
        if (n0 + l < N_NODES) a = a4[i];
        xs[swz(l, k + 0)] = a.x;
        xs[swz(l, k + 1)] = a.y;
        xs[swz(l, k + 2)] = a.z;
        xs[swz(l, k + 3)] = a.w;
    }
    __syncthreads();

#pragma unroll 2
    for (int k = 0; k < D; k++) {
        float v = xs[swz(tid, k)];
        u64t v2 = pk2(v, v);
        const ulonglong2* wr = (const ulonglong2*)(w1s + (D + k) * D);
#pragma unroll
        for (int j = 0; j < 16; j++) {
            ulonglong2 w = wr[j];
            fma2(hp[2 * j + 0], v2, w.x);
            fma2(hp[2 * j + 1], v2, w.y);
        }
    }

    float h[D];
#pragma unroll
    for (int j = 0; j < 32; j++) {
        float a, b; upk2(hp[j], a, b);
        h[2 * j + 0] = fmaxf(a, 0.f);
        h[2 * j + 1] = fmaxf(b, 0.f);
    }

    const int n = n0 + tid;
    if (n < N_NODES) {
        float* orow = out + (size_t)n * D;
#pragma unroll
        for (int jc = 0; jc < D; jc += 32) {
            u64t acc[16];
            const u64t* b2p = (const u64t*)(b2s + jc);
#pragma unroll
            for (int t = 0; t < 16; t++) acc[t] = b2p[t];
#pragma unroll
            for (int k = 0; k < D; k++) {
                u64t v2 = pk2(h[k], h[k]);
                const ulonglong2* wr = (const ulonglong2*)(w2s + k * D + jc);
#pragma unroll
                for (int t = 0; t < 8; t++) {
                    ulonglong2 w = wr[t];
                    fma2(acc[2 * t + 0], v2, w.x);
                    fma2(acc[2 * t + 1], v2, w.y);
                }
            }
#pragma unroll
            for (int t = 0; t < 8; t++) {
                ulonglong2 st; st.x = acc[2 * t]; st.y = acc[2 * t + 1];
                *(ulonglong2*)(orow + jc + 4 * t) = st;
            }
        }
    }
}

// ---------------------------------------------------------------------------
// Launch. Inputs: 0 x, 1 edge_index, 2 batch, 3..6 msg mlp, 7..10 out mlp
// ---------------------------------------------------------------------------
extern "C" void kernel_launch(void* const* d_in, const int* in_sizes, int n_in,
                              void* d_out, int out_size)
{
    const float* x      = (const float*)d_in[0];
    const void*  ei     = d_in[1];
    const float* msg_w1 = (const float*)d_in[3];
    const float* msg_b1 = (const float*)d_in[4];
    const float* msg_w2 = (const float*)d_in[5];
    const float* msg_b2 = (const float*)d_in[6];
    const float* out_w1 = (const float*)d_in[7];
    const float* out_b1 = (const float*)d_in[8];
    const float* out_w2 = (const float*)d_in[9];
    const float* out_b2 = (const float*)d_in[10];
    float*       out    = (float*)d_out;

    const int smem1 = K1_SMEM_FLOATS * sizeof(float);   // 96.5 KB
    const int smem3 = K3_SMEM_FLOATS * sizeof(float);   // 112.5 KB
    cudaFuncSetAttribute(k_msg_mlp, cudaFuncAttributeMaxDynamicSharedMemorySize, smem1);
    cudaFuncSetAttribute(k_out_mlp, cudaFuncAttributeMaxDynamicSharedMemorySize, smem3);

    const int nodeBlocks = (N_NODES + 255) / 256;

    k_zero_agg<<<(N_NODES * D / 4 + 255) / 256, 256>>>((const int*)ei);
    k_msg_mlp<<<nodeBlocks, 256, smem1>>>(x, msg_w1, msg_b1, msg_w2, msg_b2);
    {
        long long work = (long long)N_EDGES * 16;
        int blocks = (int)((work + 255) / 256);
        k_scatter<<<blocks, 256>>>(ei);
    }
    k_out_mlp<<<nodeBlocks, 256, smem3>>>(x, out_w1, out_b1, out_w2, out_b2, out);
}

// round 6
// speedup vs baseline: 1.3583x; 1.2158x over previous
#include <cuda_runtime.h>

#define N_NODES 100000
#define N_EDGES 1000000
#define D 64

// Scratch: device globals (no allocs allowed). float4 => 16B aligned.
__device__ float4 g_y4[(size_t)N_NODES * (D / 4)];    // message MLP output
__device__ float4 g_agg4[(size_t)N_NODES * (D / 4)];  // scatter-sum accumulator
__device__ int    g_ei_is64;                          // 1 if edge_index is int64

// Rotation swizzle: row l, col k stored at (l<<6) | ((k+l)&63).
// Conflict-free for BOTH row reads and column reads (8 consecutive rows at
// fixed k hit banks b, b+8, b+16, b+24).
__device__ __forceinline__ int swz(int l, int k) { return (l << 6) | ((k + l) & 63); }

// ---- packed f32x2 helpers (Blackwell dual-FP32 pipe) ----
typedef unsigned long long u64t;

__device__ __forceinline__ u64t pk2(float a, float b) {
    u64t r; asm("mov.b64 %0, {%1, %2};" : "=l"(r) : "f"(a), "f"(b)); return r;
}
__device__ __forceinline__ void upk2(u64t p, float& a, float& b) {
    asm("mov.b64 {%0, %1}, %2;" : "=f"(a), "=f"(b) : "l"(p));
}
__device__ __forceinline__ void fma2(u64t& d, u64t a, u64t b) {
    asm("fma.rn.f32x2 %0, %1, %2, %0;" : "+l"(d) : "l"(a), "l"(b));
}

// ---------------------------------------------------------------------------
// K0: zero agg + detect edge_index dtype (int64 LE => odd 32-bit words == 0)
// ---------------------------------------------------------------------------
__global__ void k_zero_agg(const int* __restrict__ ei32) {
    int idx = blockIdx.x * blockDim.x + threadIdx.x;
    const int n4 = N_NODES * (D / 4);
    if (idx < n4) g_agg4[idx] = make_float4(0.f, 0.f, 0.f, 0.f);
    if (blockIdx.x == 0 && threadIdx.x == 0) {
        int is64 = 1;
        for (int i = 0; i < 64; i++)
            if (ei32[2 * i + 1] != 0) { is64 = 0; break; }
        g_ei_is64 = is64;
    }
}

// ---------------------------------------------------------------------------
// Shared building blocks for the register-tiled MLP kernels.
// CTA = 256 threads, tile = 256 rows x 64 cols (rotation-swizzled).
// Warp w owns rows [32w, 32w+32); thread (rg=lane>>3, cg=lane&7) computes
// rows r0..r0+7 x cols c0..c0+7 with 32 packed f32x2 accumulators.
// ---------------------------------------------------------------------------

// Stage a 256x64 gmem slab (row-major float4) into the swizzled tile.
__device__ __forceinline__ void stage_tile(float* xs, const float4* src4,
                                           int n0, int tid) {
    for (int i = tid; i < (256 * D) / 4; i += 256) {
        int elem = i * 4;
        int l = elem >> 6, k = elem & 63;
        float4 v = make_float4(0.f, 0.f, 0.f, 0.f);
        if (n0 + l < N_NODES) v = src4[i];
        xs[swz(l, k + 0)] = v.x;
        xs[swz(l, k + 1)] = v.y;
        xs[swz(l, k + 2)] = v.z;
        xs[swz(l, k + 3)] = v.w;
    }
}

// One GEMM accumulation sweep: acc += tile[r0..r0+7][k] * W[k][c0..c0+7],
// k in [0,64). W row-major 64-wide.
__device__ __forceinline__ void gemm_sweep(u64t acc[8][4], const float* xs,
                                           const float* ws, int r0, int c0) {
#pragma unroll 8
    for (int k = 0; k < D; k++) {
        float a[8];
#pragma unroll
        for (int i = 0; i < 8; i++) a[i] = xs[swz(r0 + i, k)];
        const ulonglong2* wr = (const ulonglong2*)(ws + k * D + c0);
        ulonglong2 bA = wr[0], bB = wr[1];
#pragma unroll
        for (int i = 0; i < 8; i++) {
            u64t a2 = pk2(a[i], a[i]);
            fma2(acc[i][0], a2, bA.x);
            fma2(acc[i][1], a2, bA.y);
            fma2(acc[i][2], a2, bB.x);
            fma2(acc[i][3], a2, bB.y);
        }
    }
}

__device__ __forceinline__ void init_acc(u64t acc[8][4], const float* bias, int c0) {
    const u64t* bp = (const u64t*)(bias + c0);
    u64t b0 = bp[0], b1 = bp[1], b2 = bp[2], b3 = bp[3];
#pragma unroll
    for (int i = 0; i < 8; i++) {
        acc[i][0] = b0; acc[i][1] = b1; acc[i][2] = b2; acc[i][3] = b3;
    }
}

// relu(acc) -> swizzled tile rows r0..r0+7, cols c0..c0+7 (warp-private rows).
__device__ __forceinline__ void write_h(float* xs, u64t acc[8][4], int r0, int c0) {
#pragma unroll
    for (int i = 0; i < 8; i++) {
#pragma unroll
        for (int p = 0; p < 4; p++) {
            float a, b; upk2(acc[i][p], a, b);
            xs[swz(r0 + i, c0 + 2 * p + 0)] = fmaxf(a, 0.f);
            xs[swz(r0 + i, c0 + 2 * p + 1)] = fmaxf(b, 0.f);
        }
    }
}

// Store acc block to gmem rows (guarded).
__device__ __forceinline__ void store_out(float* dst, u64t acc[8][4],
                                          int n0, int r0, int c0) {
#pragma unroll
    for (int i = 0; i < 8; i++) {
        int n = n0 + r0 + i;
        if (n < N_NODES) {
            float4 v0, v1;
            upk2(acc[i][0], v0.x, v0.y); upk2(acc[i][1], v0.z, v0.w);
            upk2(acc[i][2], v1.x, v1.y); upk2(acc[i][3], v1.z, v1.w);
            *(float4*)(dst + (size_t)n * D + c0)     = v0;
            *(float4*)(dst + (size_t)n * D + c0 + 4) = v1;
        }
    }
}

// ---------------------------------------------------------------------------
// K1: node message MLP  y = relu(x @ W1 + b1) @ W2 + b2      [N,64]
// ---------------------------------------------------------------------------
#define K1_SMEM_FLOATS (256 * 64 + 4096 + 4096 + 64 + 64)

__global__ __launch_bounds__(256, 2) void k_msg_mlp(
    const float* __restrict__ x,
    const float* __restrict__ w1, const float* __restrict__ b1,
    const float* __restrict__ w2, const float* __restrict__ b2)
{
    extern __shared__ float sm[];
    float* xs  = sm;               // 256*64 swizzled tile (x, then h)
    float* w1s = xs + 256 * 64;    // 64*64
    float* w2s = w1s + 4096;       // 64*64
    float* b1s = w2s + 4096;       // 64
    float* b2s = b1s + 64;         // 64

    const int tid = threadIdx.x;
    const int n0  = blockIdx.x * 256;
    const int lane = tid & 31;
    const int r0 = (tid >> 5) * 32 + (lane >> 3) * 8;
    const int c0 = (lane & 7) * 8;

    for (int i = tid; i < 4096 / 4; i += 256) {
        ((float4*)w1s)[i] = ((const float4*)w1)[i];
        ((float4*)w2s)[i] = ((const float4*)w2)[i];
    }
    if (tid < 64) { b1s[tid] = b1[tid]; b2s[tid] = b2[tid]; }
    stage_tile(xs, (const float4*)(x + (size_t)n0 * D), n0, tid);
    __syncthreads();

    // layer 1
    u64t acc[8][4];
    init_acc(acc, b1s, c0);
    gemm_sweep(acc, xs, w1s, r0, c0);

    // h -> tile (rows are warp-private: warp-level sync suffices)
    __syncwarp();
    write_h(xs, acc, r0, c0);
    __syncwarp();

    // layer 2
    init_acc(acc, b2s, c0);
    gemm_sweep(acc, xs, w2s, r0, c0);

    store_out((float*)g_y4, acc, n0, r0, c0);
}

// ---------------------------------------------------------------------------
// K2: scatter  agg[col] += y[row]  via red.global.add.v4.f32
// ---------------------------------------------------------------------------
__global__ __launch_bounds__(256) void k_scatter(const void* __restrict__ ei_raw)
{
    long long tid = (long long)blockIdx.x * blockDim.x + threadIdx.x;
    if (tid >= (long long)N_EDGES * 16) return;
    int e = (int)(tid >> 4);
    int c = (int)(tid & 15);

    int row, col;
    if (g_ei_is64) {
        const long long* ei = (const long long*)ei_raw;
        row = (int)ei[e];
        col = (int)ei[N_EDGES + e];
    } else {
        const int* ei = (const int*)ei_raw;
        row = ei[e];
        col = ei[N_EDGES + e];
    }
    if ((unsigned)row >= N_NODES || (unsigned)col >= N_NODES) return;

    const float4 v = g_y4[(size_t)row * (D / 4) + c];
    float4* p = g_agg4 + (size_t)col * (D / 4) + c;
    asm volatile("red.global.add.v4.f32 [%0], {%1,%2,%3,%4};"
                 :: "l"(p), "f"(v.x), "f"(v.y), "f"(v.z), "f"(v.w)
                 : "memory");
}

// ---------------------------------------------------------------------------
// K3: output MLP  out = relu([x,agg] @ W1 + b1) @ W2 + b2     [N,64]
// Two-pass layer 1: sweep x tile with W1[0:64], restage agg, sweep W1[64:128].
// ---------------------------------------------------------------------------
#define K3_SMEM_FLOATS (256 * 64 + 8192 + 4096 + 64 + 64)

__global__ __launch_bounds__(256, 2) void k_out_mlp(
    const float* __restrict__ x,
    const float* __restrict__ w1, const float* __restrict__ b1,
    const float* __restrict__ w2, const float* __restrict__ b2,
    float* __restrict__ out)
{
    extern __shared__ float sm[];
    float* xs  = sm;               // 256*64 swizzled tile (x, agg, then h)
    float* w1s = xs + 256 * 64;    // 128*64
    float* w2s = w1s + 8192;       // 64*64
    float* b1s = w2s + 4096;       // 64
    float* b2s = b1s + 64;         // 64

    const int tid = threadIdx.x;
    const int n0  = blockIdx.x * 256;
    const int lane = tid & 31;
    const int r0 = (tid >> 5) * 32 + (lane >> 3) * 8;
    const int c0 = (lane & 7) * 8;

    for (int i = tid; i < 8192 / 4; i += 256)
        ((float4*)w1s)[i] = ((const float4*)w1)[i];
    for (int i = tid; i < 4096 / 4; i += 256)
        ((float4*)w2s)[i] = ((const float4*)w2)[i];
    if (tid < 64) { b1s[tid] = b1[tid]; b2s[tid] = b2[tid]; }

    // pass A: x tile, W1 rows 0..63
    stage_tile(xs, (const float4*)(x + (size_t)n0 * D), n0, tid);
    __syncthreads();

    u64t acc[8][4];
    init_acc(acc, b1s, c0);
    gemm_sweep(acc, xs, w1s, r0, c0);
    __syncthreads();   // all warps done reading x tile

    // pass B: agg tile, W1 rows 64..127
    stage_tile(xs, (const float4*)(g_agg4 + (size_t)n0 * (D / 4)), n0, tid);
    __syncthreads();
    gemm_sweep(acc, xs, w1s + D * D, r0, c0);

    // h -> tile (warp-private rows)
    __syncwarp();
    write_h(xs, acc, r0, c0);
    __syncwarp();

    // layer 2
    init_acc(acc, b2s, c0);
    gemm_sweep(acc, xs, w2s, r0, c0);

    store_out(out, acc, n0, r0, c0);
}

// ---------------------------------------------------------------------------
// Launch. Inputs: 0 x, 1 edge_index, 2 batch, 3..6 msg mlp, 7..10 out mlp
// ---------------------------------------------------------------------------
extern "C" void kernel_launch(void* const* d_in, const int* in_sizes, int n_in,
                              void* d_out, int out_size)
{
    const float* x      = (const float*)d_in[0];
    const void*  ei     = d_in[1];
    const float* msg_w1 = (const float*)d_in[3];
    const float* msg_b1 = (const float*)d_in[4];
    const float* msg_w2 = (const float*)d_in[5];
    const float* msg_b2 = (const float*)d_in[6];
    const float* out_w1 = (const float*)d_in[7];
    const float* out_b1 = (const float*)d_in[8];
    const float* out_w2 = (const float*)d_in[9];
    const float* out_b2 = (const float*)d_in[10];
    float*       out    = (float*)d_out;

    const int smem1 = K1_SMEM_FLOATS * sizeof(float);   // 96.5 KB
    const int smem3 = K3_SMEM_FLOATS * sizeof(float);   // 112.5 KB
    cudaFuncSetAttribute(k_msg_mlp, cudaFuncAttributeMaxDynamicSharedMemorySize, smem1);
    cudaFuncSetAttribute(k_out_mlp, cudaFuncAttributeMaxDynamicSharedMemorySize, smem3);

    const int nodeBlocks = (N_NODES + 255) / 256;   // 391

    k_zero_agg<<<(N_NODES * D / 4 + 255) / 256, 256>>>((const int*)ei);
    k_msg_mlp<<<nodeBlocks, 256, smem1>>>(x, msg_w1, msg_b1, msg_w2, msg_b2);
    {
        long long work = (long long)N_EDGES * 16;
        int blocks = (int)((work + 255) / 256);
        k_scatter<<<blocks, 256>>>(ei);
    }
    k_out_mlp<<<nodeBlocks, 256, smem3>>>(x, out_w1, out_b1, out_w2, out_b2, out);
}